// round 2
// baseline (speedup 1.0000x reference)
#include <cuda_runtime.h>
#include <math.h>

// Problem constants
#define BB 2
#define LL 2048
#define DD 1024
#define HH 16
#define DHD 64
#define ROWS (BB*LL)        // 4096
#define EPS 1e-5f

// ---------------- scratch (device globals; no allocation) ----------------
__device__ float g_h[ROWS * DD];          // 16 MB
__device__ float g_qkv[ROWS * 3 * DD];    // 48 MB
__device__ float g_q[BB * HH * LL * DHD]; // 16 MB  [B,H,L,DH]
__device__ float g_k[BB * HH * LL * DHD]; // 16 MB
__device__ float g_v[BB * HH * LL * DHD]; // 16 MB
__device__ float g_ctx[ROWS * DD];        // 16 MB  [B,L,H,DH]

// ---------------- block reduce (sum of two values) ----------------
__device__ __forceinline__ void block_reduce2(float& a, float& b, float* red) {
    int lane = threadIdx.x & 31;
    int w    = threadIdx.x >> 5;
#pragma unroll
    for (int o = 16; o > 0; o >>= 1) {
        a += __shfl_xor_sync(0xffffffffu, a, o);
        b += __shfl_xor_sync(0xffffffffu, b, o);
    }
    if (lane == 0) { red[w] = a; red[8 + w] = b; }
    __syncthreads();
    if (threadIdx.x == 0) {
        float sa = 0.f, sb = 0.f;
#pragma unroll
        for (int i = 0; i < 8; i++) { sa += red[i]; sb += red[8 + i]; }
        red[16] = sa; red[17] = sb;
    }
    __syncthreads();
    a = red[16]; b = red[17];
    __syncthreads();
}

// ---------------- LN1: h = LN(x)*w + b ----------------
__global__ __launch_bounds__(256) void ln1_kernel(
    const float* __restrict__ x, const float* __restrict__ w,
    const float* __restrict__ bias, float* __restrict__ out)
{
    __shared__ float red[20];
    int row = blockIdx.x;
    const float4* xr = (const float4*)(x + (size_t)row * DD);
    float4 v = xr[threadIdx.x];
    float s  = v.x + v.y + v.z + v.w;
    float s2 = v.x*v.x + v.y*v.y + v.z*v.z + v.w*v.w;
    block_reduce2(s, s2, red);
    float mu  = s * (1.0f / DD);
    float var = s2 * (1.0f / DD) - mu * mu;
    float inv = rsqrtf(var + EPS);
    const float4* w4 = (const float4*)w;
    const float4* b4 = (const float4*)bias;
    float4 ww = w4[threadIdx.x], bb2 = b4[threadIdx.x];
    float4 o;
    o.x = (v.x - mu) * inv * ww.x + bb2.x;
    o.y = (v.y - mu) * inv * ww.y + bb2.y;
    o.z = (v.z - mu) * inv * ww.z + bb2.z;
    o.w = (v.w - mu) * inv * ww.w + bb2.w;
    ((float4*)(out + (size_t)row * DD))[threadIdx.x] = o;
}

// ---------------- NT SGEMM: C[M,N] = A[M,K] * B[N,K]^T ----------------
// 128x128 tile, BK=8, 256 threads, 8x8 microtile
#define BM 128
#define BN 128
#define BKK 8
__global__ __launch_bounds__(256) void gemm_nt(
    const float* __restrict__ A, const float* __restrict__ B,
    float* __restrict__ C, int M, int N, int K)
{
    __shared__ float As[BKK][BM];
    __shared__ float Bs[BKK][BN];
    int t  = threadIdx.x;
    int tr = t >> 4;        // 0..15
    int tc = t & 15;        // 0..15
    int m0 = blockIdx.y * BM;
    int n0 = blockIdx.x * BN;

    int lr = t >> 1;            // 0..127
    int lk = (t & 1) * 4;       // 0 or 4
    const float* Ab = A + (size_t)(m0 + lr) * K + lk;
    const float* Bb = B + (size_t)(n0 + lr) * K + lk;

    float acc[8][8];
#pragma unroll
    for (int i = 0; i < 8; i++)
#pragma unroll
        for (int j = 0; j < 8; j++) acc[i][j] = 0.f;

    for (int k0 = 0; k0 < K; k0 += BKK) {
        float4 a = *(const float4*)(Ab + k0);
        float4 b = *(const float4*)(Bb + k0);
        __syncthreads();
        As[lk+0][lr] = a.x; As[lk+1][lr] = a.y; As[lk+2][lr] = a.z; As[lk+3][lr] = a.w;
        Bs[lk+0][lr] = b.x; Bs[lk+1][lr] = b.y; Bs[lk+2][lr] = b.z; Bs[lk+3][lr] = b.w;
        __syncthreads();
#pragma unroll
        for (int k = 0; k < BKK; k++) {
            float4 a0 = *(const float4*)&As[k][tr*8];
            float4 a1 = *(const float4*)&As[k][tr*8+4];
            float4 b0 = *(const float4*)&Bs[k][tc*8];
            float4 b1 = *(const float4*)&Bs[k][tc*8+4];
            float ar[8] = {a0.x,a0.y,a0.z,a0.w,a1.x,a1.y,a1.z,a1.w};
            float br[8] = {b0.x,b0.y,b0.z,b0.w,b1.x,b1.y,b1.z,b1.w};
#pragma unroll
            for (int i = 0; i < 8; i++)
#pragma unroll
                for (int j = 0; j < 8; j++)
                    acc[i][j] += ar[i] * br[j];
        }
    }
#pragma unroll
    for (int i = 0; i < 8; i++) {
        float* Cr = C + (size_t)(m0 + tr*8 + i) * N + n0 + tc*8;
        float4 o0 = {acc[i][0], acc[i][1], acc[i][2], acc[i][3]};
        float4 o1 = {acc[i][4], acc[i][5], acc[i][6], acc[i][7]};
        ((float4*)Cr)[0] = o0;
        ((float4*)(Cr+4))[0] = o1;
    }
}

// ---------------- Q/K LN (over full D) + RoPE + scatter; V scatter ----------------
__global__ __launch_bounds__(256) void qk_rope_kernel(
    const float* __restrict__ qkv,
    const float* __restrict__ qw, const float* __restrict__ kw,
    float* __restrict__ qo, float* __restrict__ ko, float* __restrict__ vo)
{
    __shared__ float qn[DD];
    __shared__ float kn[DD];
    __shared__ float red[20];
    int row = blockIdx.x;          // b*L + l
    int b = row / LL;
    int l = row % LL;
    int t = threadIdx.x;
    const float* qr = qkv + (size_t)row * (3*DD);
    const float* kr = qr + DD;
    const float* vr = qr + 2*DD;

    float4 qv = ((const float4*)qr)[t];
    float4 kv = ((const float4*)kr)[t];

    // q stats
    float s  = qv.x + qv.y + qv.z + qv.w;
    float s2 = qv.x*qv.x + qv.y*qv.y + qv.z*qv.z + qv.w*qv.w;
    block_reduce2(s, s2, red);
    float qmu = s * (1.0f/DD);
    float qinv = rsqrtf(s2 * (1.0f/DD) - qmu*qmu + EPS);
    // k stats
    float u  = kv.x + kv.y + kv.z + kv.w;
    float u2 = kv.x*kv.x + kv.y*kv.y + kv.z*kv.z + kv.w*kv.w;
    block_reduce2(u, u2, red);
    float kmu = u * (1.0f/DD);
    float kinv = rsqrtf(u2 * (1.0f/DD) - kmu*kmu + EPS);

    float4 qwv = ((const float4*)qw)[t];
    float4 kwv = ((const float4*)kw)[t];
    int d0 = 4 * t;
    qn[d0+0] = (qv.x - qmu)*qinv*qwv.x;
    qn[d0+1] = (qv.y - qmu)*qinv*qwv.y;
    qn[d0+2] = (qv.z - qmu)*qinv*qwv.z;
    qn[d0+3] = (qv.w - qmu)*qinv*qwv.w;
    kn[d0+0] = (kv.x - kmu)*kinv*kwv.x;
    kn[d0+1] = (kv.y - kmu)*kinv*kwv.y;
    kn[d0+2] = (kv.z - kmu)*kinv*kwv.z;
    kn[d0+3] = (kv.w - kmu)*kinv*kwv.w;
    __syncthreads();

#pragma unroll
    for (int e = 0; e < 4; e++) {
        int dd = d0 + e;
        int h  = dd >> 6;
        int j  = dd & 63;
        int jj = j & 31;
        float inv_freq = __powf(10000.0f, -(float)(2*jj) * (1.0f/64.0f));
        float ang = (float)l * inv_freq;
        float sn, cs;
        sincosf(ang, &sn, &cs);
        int pd = (j < 32) ? dd + 32 : dd - 32;
        float qvv = qn[dd], qp = qn[pd];
        float kvv = kn[dd], kp = kn[pd];
        float rq = (j < 32) ? (qvv*cs - qp*sn) : (qvv*cs + qp*sn);
        float rk = (j < 32) ? (kvv*cs - kp*sn) : (kvv*cs + kp*sn);
        size_t oidx = ((size_t)(b*HH + h) * LL + l) * DHD + j;
        qo[oidx] = rq;
        ko[oidx] = rk;
        vo[oidx] = vr[dd];
    }
}

// ---------------- flash attention with seq_id block-diagonal skip ----------------
// grid: (L/64, B*H), 256 threads (16x16). smem: Qt[64][64] | Kt[64][64] (aliased Ps[64][65]) | Vs[64][64] | seqq[64] | seqk[64]
#define ATT_SMEM_FLOATS (4096 + 4160 + 4096 + 128)
__global__ __launch_bounds__(256) void attn_kernel(
    const float* __restrict__ Q, const float* __restrict__ K,
    const float* __restrict__ V, const int* __restrict__ seq_id,
    float* __restrict__ ctx)
{
    extern __shared__ float sm[];
    float* Qt = sm;                 // [k][r] : k*64 + r
    float* Kt = sm + 4096;          // [k][c] : k*64 + c
    float* Ps = Kt;                 // [r][c] : r*65 + c (aliases Kt)
    float* Vs = sm + 4096 + 4160;   // [c][d] : c*64 + d
    int* seqq = (int*)(sm + 4096 + 4160 + 4096);
    int* seqk = seqq + 64;

    int t  = threadIdx.x;
    int ty = t >> 4;    // 0..15 -> rows 4*ty..
    int tx = t & 15;    // 0..15 -> cols 4*tx..
    int q0 = blockIdx.x * 64;
    int bh = blockIdx.y;
    int b  = bh >> 4;
    int h  = bh & 15;

    const float* Qg = Q + ((size_t)bh * LL + q0) * DHD;
    const int* seqb = seq_id + (size_t)b * LL;

    // load Q transposed + query seq ids
#pragma unroll
    for (int i = 0; i < 4; i++) {
        int idx = t + i * 256;
        int r  = idx >> 4;
        int jv = idx & 15;
        float4 q4 = *(const float4*)(Qg + r*DHD + 4*jv);
        Qt[(4*jv+0)*64 + r] = q4.x;
        Qt[(4*jv+1)*64 + r] = q4.y;
        Qt[(4*jv+2)*64 + r] = q4.z;
        Qt[(4*jv+3)*64 + r] = q4.w;
    }
    if (t < 64) seqq[t] = seqb[q0 + t];
    __syncthreads();

    int qmin = seqq[0], qmax = seqq[63];
    int sq[4];
#pragma unroll
    for (int i = 0; i < 4; i++) sq[i] = seqq[4*ty + i];

    float m[4], lsum[4], acc[4][4];
#pragma unroll
    for (int i = 0; i < 4; i++) {
        m[i] = -1e30f; lsum[i] = 0.f;
#pragma unroll
        for (int j = 0; j < 4; j++) acc[i][j] = 0.f;
    }
    const float scale = 0.125f;   // 1/sqrt(64)

    for (int kt = 0; kt < LL/64; kt++) {
        int k0 = kt * 64;
        int kmin = seqb[k0], kmax = seqb[k0 + 63];
        if (kmax < qmin || kmin > qmax) continue;   // sorted seq_id -> block-diagonal skip

        __syncthreads();  // prior PV done before Kt/Vs overwrite
        const float* Kg = K + ((size_t)bh * LL + k0) * DHD;
        const float* Vg = V + ((size_t)bh * LL + k0) * DHD;
#pragma unroll
        for (int i = 0; i < 4; i++) {
            int idx = t + i * 256;
            int c  = idx >> 4;
            int jv = idx & 15;
            float4 k4 = *(const float4*)(Kg + c*DHD + 4*jv);
            Kt[(4*jv+0)*64 + c] = k4.x;
            Kt[(4*jv+1)*64 + c] = k4.y;
            Kt[(4*jv+2)*64 + c] = k4.z;
            Kt[(4*jv+3)*64 + c] = k4.w;
            *(float4*)(Vs + c*64 + 4*jv) = *(const float4*)(Vg + c*DHD + 4*jv);
        }
        if (t < 64) seqk[t] = seqb[k0 + t];
        __syncthreads();

        // S = Q K^T
        float s[4][4];
#pragma unroll
        for (int i = 0; i < 4; i++)
#pragma unroll
            for (int j = 0; j < 4; j++) s[i][j] = 0.f;
#pragma unroll 8
        for (int k = 0; k < 64; k++) {
            float4 qv = *(const float4*)&Qt[k*64 + 4*ty];
            float4 kv = *(const float4*)&Kt[k*64 + 4*tx];
            float qa[4] = {qv.x,qv.y,qv.z,qv.w};
            float ka[4] = {kv.x,kv.y,kv.z,kv.w};
#pragma unroll
            for (int i = 0; i < 4; i++)
#pragma unroll
                for (int j = 0; j < 4; j++)
                    s[i][j] += qa[i] * ka[j];
        }

        int sk[4];
#pragma unroll
        for (int j = 0; j < 4; j++) sk[j] = seqk[4*tx + j];

        bool ok[4][4];
#pragma unroll
        for (int i = 0; i < 4; i++)
#pragma unroll
            for (int j = 0; j < 4; j++) {
                ok[i][j] = (sq[i] == sk[j]);
                s[i][j] = ok[i][j] ? s[i][j]*scale : -1e30f;
            }

        // online softmax update
        float p[4][4];
#pragma unroll
        for (int i = 0; i < 4; i++) {
            float rm = fmaxf(fmaxf(s[i][0], s[i][1]), fmaxf(s[i][2], s[i][3]));
#pragma unroll
            for (int o = 1; o <= 8; o <<= 1)
                rm = fmaxf(rm, __shfl_xor_sync(0xffffffffu, rm, o));
            float mn = fmaxf(m[i], rm);
            float corr = __expf(m[i] - mn);
            float rs = 0.f;
#pragma unroll
            for (int j = 0; j < 4; j++) {
                p[i][j] = ok[i][j] ? __expf(s[i][j] - mn) : 0.f;
                rs += p[i][j];
            }
#pragma unroll
            for (int o = 1; o <= 8; o <<= 1)
                rs += __shfl_xor_sync(0xffffffffu, rs, o);
            lsum[i] = lsum[i] * corr + rs;
#pragma unroll
            for (int j = 0; j < 4; j++) acc[i][j] *= corr;
            m[i] = mn;
        }

        __syncthreads();   // Kt reads done before Ps overwrite (aliased)
#pragma unroll
        for (int i = 0; i < 4; i++)
#pragma unroll
            for (int j = 0; j < 4; j++)
                Ps[(4*ty+i)*65 + 4*tx + j] = p[i][j];
        __syncthreads();

        // acc += P * V
#pragma unroll 8
        for (int c = 0; c < 64; c++) {
            float4 vv = *(const float4*)&Vs[c*64 + 4*tx];
#pragma unroll
            for (int i = 0; i < 4; i++) {
                float pi = Ps[(4*ty+i)*65 + c];
                acc[i][0] += pi * vv.x;
                acc[i][1] += pi * vv.y;
                acc[i][2] += pi * vv.z;
                acc[i][3] += pi * vv.w;
            }
        }
    }

    // epilogue -> ctx [B, L, H, DH]
#pragma unroll
    for (int i = 0; i < 4; i++) {
        float invl = 1.0f / lsum[i];
        float4 o = {acc[i][0]*invl, acc[i][1]*invl, acc[i][2]*invl, acc[i][3]*invl};
        size_t oidx = (((size_t)b*LL + q0 + 4*ty + i) * HH + h) * DHD + 4*tx;
        *(float4*)(ctx + oidx) = o;
    }
}

// ---------------- launch ----------------
extern "C" void kernel_launch(void* const* d_in, const int* in_sizes, int n_in,
                              void* d_out, int out_size)
{
    const float* x     = (const float*)d_in[0];
    const int*   seq   = (const int*)  d_in[1];
    const float* ln1w  = (const float*)d_in[2];
    const float* ln1b  = (const float*)d_in[3];
    const float* wqkv  = (const float*)d_in[4];
    const float* qlnw  = (const float*)d_in[5];
    const float* klnw  = (const float*)d_in[6];
    const float* outw  = (const float*)d_in[7];
    float* out = (float*)d_out;

    float *h, *qkv, *q, *k, *v, *ctx;
    cudaGetSymbolAddress((void**)&h,   g_h);
    cudaGetSymbolAddress((void**)&qkv, g_qkv);
    cudaGetSymbolAddress((void**)&q,   g_q);
    cudaGetSymbolAddress((void**)&k,   g_k);
    cudaGetSymbolAddress((void**)&v,   g_v);
    cudaGetSymbolAddress((void**)&ctx, g_ctx);

    cudaFuncSetAttribute(attn_kernel, cudaFuncAttributeMaxDynamicSharedMemorySize,
                         ATT_SMEM_FLOATS * 4);

    ln1_kernel<<<ROWS, 256>>>(x, ln1w, ln1b, h);
    gemm_nt<<<dim3(3*DD/BN, ROWS/BM), 256>>>(h, wqkv, qkv, ROWS, 3*DD, DD);
    qk_rope_kernel<<<ROWS, 256>>>(qkv, qlnw, klnw, q, k, v);
    attn_kernel<<<dim3(LL/64, BB*HH), 256, ATT_SMEM_FLOATS*4>>>(q, k, v, seq, ctx);
    gemm_nt<<<dim3(DD/BN, ROWS/BM), 256>>>(ctx, outw, out, ROWS, DD, DD);
}

// round 5
// speedup vs baseline: 3.4169x; 3.4169x over previous
#include <cuda_runtime.h>
#include <cuda_bf16.h>
#include <math.h>
#include <stdint.h>

// Problem constants
#define BB 2
#define LL 2048
#define DD 1024
#define HH 16
#define DHD 64
#define ROWS (BB*LL)        // 4096
#define EPS 1e-5f

// ---------------- scratch (device globals; no allocation) ----------------
__device__ float g_qkv[ROWS * 3 * DD];    // 48 MB
__device__ float g_q[BB * HH * LL * DHD]; // 16 MB  [B,H,L,DH]
__device__ float g_k[BB * HH * LL * DHD]; // 16 MB
__device__ float g_v[BB * HH * LL * DHD]; // 16 MB
__device__ __nv_bfloat16 g_hh[ROWS * DD];        // 8 MB  LN1 out hi
__device__ __nv_bfloat16 g_hl[ROWS * DD];        // 8 MB  LN1 out lo
__device__ __nv_bfloat16 g_wqh[3 * DD * DD];     // 6 MB
__device__ __nv_bfloat16 g_wql[3 * DD * DD];     // 6 MB
__device__ __nv_bfloat16 g_ctxh[ROWS * DD];      // 8 MB
__device__ __nv_bfloat16 g_ctxl[ROWS * DD];      // 8 MB
__device__ __nv_bfloat16 g_owh[DD * DD];         // 2 MB
__device__ __nv_bfloat16 g_owl[DD * DD];         // 2 MB

// =================== helpers ===================
__device__ __forceinline__ uint32_t smem_u32(const void* p) {
    uint32_t a;
    asm("{ .reg .u64 t; cvta.to.shared.u64 t, %1; cvt.u32.u64 %0, t; }" : "=r"(a) : "l"(p));
    return a;
}
__device__ __forceinline__ uint32_t pack_bf2(float x, float y) {
    __nv_bfloat162 v = __floats2bfloat162_rn(x, y);
    return *(uint32_t*)&v;
}
__device__ __forceinline__ void cpasync16(uint32_t dst, const void* src) {
    asm volatile("cp.async.cg.shared.global [%0], [%1], 16;" :: "r"(dst), "l"(src));
}
__device__ __forceinline__ void ldsm4(uint32_t* r, uint32_t addr) {
    asm volatile("ldmatrix.sync.aligned.m8n8.x4.shared.b16 {%0,%1,%2,%3}, [%4];"
        : "=r"(r[0]), "=r"(r[1]), "=r"(r[2]), "=r"(r[3]) : "r"(addr));
}
__device__ __forceinline__ void ldsm2(uint32_t* r, uint32_t addr) {
    asm volatile("ldmatrix.sync.aligned.m8n8.x2.shared.b16 {%0,%1}, [%2];"
        : "=r"(r[0]), "=r"(r[1]) : "r"(addr));
}
__device__ __forceinline__ void mma16816(float* d, const uint32_t* a, const uint32_t* b) {
    asm volatile(
        "mma.sync.aligned.m16n8k16.row.col.f32.bf16.bf16.f32 "
        "{%0,%1,%2,%3}, {%4,%5,%6,%7}, {%8,%9}, {%0,%1,%2,%3};"
        : "+f"(d[0]), "+f"(d[1]), "+f"(d[2]), "+f"(d[3])
        : "r"(a[0]), "r"(a[1]), "r"(a[2]), "r"(a[3]), "r"(b[0]), "r"(b[1]));
}

// =================== split-bf16 NT GEMM via mma.sync ===================
// C[M,N] = (Ah+Al)[M,K] * (Bh+Bl)[N,K]^T, dropping Al*Bl. fp32 accum.
// 128x128 tile, BK=64, 3-stage cp.async pipeline, 256 threads.
#define GSTAGE_BYTES 65536          // Ah16K Al16K Bh16K Bl16K
#define GEMM_SMEM (3 * GSTAGE_BYTES)

__device__ __forceinline__ void load_stage(
    uint32_t sbase,
    const __nv_bfloat16* __restrict__ Ah, const __nv_bfloat16* __restrict__ Al,
    const __nv_bfloat16* __restrict__ Bh, const __nv_bfloat16* __restrict__ Bl,
    int m0, int n0, int K, int k0, int t)
{
#pragma unroll
    for (int i = 0; i < 4; i++) {
        int chunk = t + i * 256;        // 0..1023
        int row = chunk >> 3;           // 0..127
        int c16 = chunk & 7;            // 0..7  (16B chunks of 128B row)
        uint32_t soff = (uint32_t)(row << 7) + (uint32_t)((c16 << 4) ^ ((row & 7) << 4));
        size_t ga = (size_t)(m0 + row) * K + k0 + c16 * 8;
        size_t gb = (size_t)(n0 + row) * K + k0 + c16 * 8;
        cpasync16(sbase + soff,         Ah + ga);
        cpasync16(sbase + 16384 + soff, Al + ga);
        cpasync16(sbase + 32768 + soff, Bh + gb);
        cpasync16(sbase + 49152 + soff, Bl + gb);
    }
}

__global__ __launch_bounds__(256, 1) void gemm_bf16s(
    const __nv_bfloat16* __restrict__ Ah, const __nv_bfloat16* __restrict__ Al,
    const __nv_bfloat16* __restrict__ Bh, const __nv_bfloat16* __restrict__ Bl,
    float* __restrict__ C, int M, int N, int K)
{
    extern __shared__ char dsm[];
    uint32_t sb = smem_u32(dsm);
    int t = threadIdx.x;
    int lane = t & 31, wid = t >> 5;
    int m0 = blockIdx.y * 128, n0 = blockIdx.x * 128;
    int wm = (wid >> 1) * 32;    // 0,32,64,96
    int wn = (wid & 1) * 64;     // 0,64

    float acc[2][8][4];
#pragma unroll
    for (int a = 0; a < 2; a++)
#pragma unroll
        for (int b = 0; b < 8; b++)
#pragma unroll
            for (int c = 0; c < 4; c++) acc[a][b][c] = 0.f;

    const int NC = K / 64;
    load_stage(sb + 0 * GSTAGE_BYTES, Ah, Al, Bh, Bl, m0, n0, K, 0, t);
    asm volatile("cp.async.commit_group;" ::: "memory");
    load_stage(sb + 1 * GSTAGE_BYTES, Ah, Al, Bh, Bl, m0, n0, K, 64, t);
    asm volatile("cp.async.commit_group;" ::: "memory");

    int arow = wm + (lane & 15);
    uint32_t axor = (uint32_t)((lane & 7) << 4);
    uint32_t ah16 = (uint32_t)((lane >> 4) << 4);
    int brow = wn + (lane & 7);
    uint32_t bh16 = (uint32_t)(((lane >> 3) & 1) << 4);

    for (int kc = 0; kc < NC; kc++) {
        int ls = kc + 2;
        if (ls < NC)
            load_stage(sb + (ls % 3) * GSTAGE_BYTES, Ah, Al, Bh, Bl, m0, n0, K, ls * 64, t);
        asm volatile("cp.async.commit_group;" ::: "memory");
        asm volatile("cp.async.wait_group 2;" ::: "memory");
        __syncthreads();

        uint32_t st = sb + (kc % 3) * GSTAGE_BYTES;
#pragma unroll
        for (int ks = 0; ks < 4; ks++) {
            uint32_t ksB = (uint32_t)(ks * 32);
            uint32_t ahf[2][4], alf[2][4];
#pragma unroll
            for (int mt = 0; mt < 2; mt++) {
                uint32_t ra = st + (uint32_t)((arow + mt * 16) << 7) + ((ksB + ah16) ^ axor);
                ldsm4(ahf[mt], ra);
                ldsm4(alf[mt], ra + 16384);
            }
            uint32_t bhf[8][2], blf[8][2];
#pragma unroll
            for (int nt = 0; nt < 8; nt++) {
                uint32_t rb = st + 32768 + (uint32_t)((brow + nt * 8) << 7) + ((ksB + bh16) ^ axor);
                ldsm2(bhf[nt], rb);
                ldsm2(blf[nt], rb + 16384);
            }
#pragma unroll
            for (int mt = 0; mt < 2; mt++)
#pragma unroll
                for (int nt = 0; nt < 8; nt++)
                    mma16816(acc[mt][nt], ahf[mt], bhf[nt]);
#pragma unroll
            for (int mt = 0; mt < 2; mt++)
#pragma unroll
                for (int nt = 0; nt < 8; nt++)
                    mma16816(acc[mt][nt], ahf[mt], blf[nt]);
#pragma unroll
            for (int mt = 0; mt < 2; mt++)
#pragma unroll
                for (int nt = 0; nt < 8; nt++)
                    mma16816(acc[mt][nt], alf[mt], bhf[nt]);
        }
        __syncthreads();
    }

    // epilogue
    int crow = lane >> 2;
    int ccol = (lane & 3) * 2;
#pragma unroll
    for (int mt = 0; mt < 2; mt++)
#pragma unroll
        for (int nt = 0; nt < 8; nt++) {
            int col = n0 + wn + nt * 8 + ccol;
            float* p0 = C + (size_t)(m0 + wm + mt * 16 + crow) * N + col;
            float* p1 = C + (size_t)(m0 + wm + mt * 16 + crow + 8) * N + col;
            float2 v0 = { acc[mt][nt][0], acc[mt][nt][1] };
            float2 v1 = { acc[mt][nt][2], acc[mt][nt][3] };
            *(float2*)p0 = v0;
            *(float2*)p1 = v1;
        }
}

// ---------------- generic fp32 -> bf16 hi/lo split ----------------
__global__ __launch_bounds__(256) void split_kernel(
    const float* __restrict__ in, __nv_bfloat16* __restrict__ hi,
    __nv_bfloat16* __restrict__ lo)
{
    int i = (blockIdx.x * 256 + threadIdx.x) * 4;
    float4 v = *(const float4*)(in + i);
    __nv_bfloat16 hx = __float2bfloat16(v.x), hy = __float2bfloat16(v.y);
    __nv_bfloat16 hz = __float2bfloat16(v.z), hw = __float2bfloat16(v.w);
    uint2 hp = make_uint2(pack_bf2(v.x, v.y), pack_bf2(v.z, v.w));
    uint2 lp = make_uint2(
        pack_bf2(v.x - __bfloat162float(hx), v.y - __bfloat162float(hy)),
        pack_bf2(v.z - __bfloat162float(hz), v.w - __bfloat162float(hw)));
    *(uint2*)(hi + i) = hp;
    *(uint2*)(lo + i) = lp;
}

// ---------------- block reduce (sum of two values) ----------------
__device__ __forceinline__ void block_reduce2(float& a, float& b, float* red) {
    int lane = threadIdx.x & 31;
    int w    = threadIdx.x >> 5;
#pragma unroll
    for (int o = 16; o > 0; o >>= 1) {
        a += __shfl_xor_sync(0xffffffffu, a, o);
        b += __shfl_xor_sync(0xffffffffu, b, o);
    }
    if (lane == 0) { red[w] = a; red[8 + w] = b; }
    __syncthreads();
    if (threadIdx.x == 0) {
        float sa = 0.f, sb = 0.f;
#pragma unroll
        for (int i = 0; i < 8; i++) { sa += red[i]; sb += red[8 + i]; }
        red[16] = sa; red[17] = sb;
    }
    __syncthreads();
    a = red[16]; b = red[17];
    __syncthreads();
}

// ---------------- LN1 with fused bf16 hi/lo split output ----------------
__global__ __launch_bounds__(256) void ln1_split_kernel(
    const float* __restrict__ x, const float* __restrict__ w,
    const float* __restrict__ bias,
    __nv_bfloat16* __restrict__ hh, __nv_bfloat16* __restrict__ hl)
{
    __shared__ float red[20];
    int row = blockIdx.x;
    const float4* xr = (const float4*)(x + (size_t)row * DD);
    float4 v = xr[threadIdx.x];
    float s  = v.x + v.y + v.z + v.w;
    float s2 = v.x*v.x + v.y*v.y + v.z*v.z + v.w*v.w;
    block_reduce2(s, s2, red);
    float mu  = s * (1.0f / DD);
    float var = s2 * (1.0f / DD) - mu * mu;
    float inv = rsqrtf(var + EPS);
    const float4* w4 = (const float4*)w;
    const float4* b4 = (const float4*)bias;
    float4 ww = w4[threadIdx.x], bb2 = b4[threadIdx.x];
    float4 o;
    o.x = (v.x - mu) * inv * ww.x + bb2.x;
    o.y = (v.y - mu) * inv * ww.y + bb2.y;
    o.z = (v.z - mu) * inv * ww.z + bb2.z;
    o.w = (v.w - mu) * inv * ww.w + bb2.w;
    __nv_bfloat16 hx = __float2bfloat16(o.x), hy = __float2bfloat16(o.y);
    __nv_bfloat16 hz = __float2bfloat16(o.z), hw = __float2bfloat16(o.w);
    uint2 hp = make_uint2(pack_bf2(o.x, o.y), pack_bf2(o.z, o.w));
    uint2 lp = make_uint2(
        pack_bf2(o.x - __bfloat162float(hx), o.y - __bfloat162float(hy)),
        pack_bf2(o.z - __bfloat162float(hz), o.w - __bfloat162float(hw)));
    size_t off = (size_t)row * DD + threadIdx.x * 4;
    *(uint2*)(hh + off) = hp;
    *(uint2*)(hl + off) = lp;
}

// ---------------- Q/K LN (over full D) + RoPE + scatter; V scatter ----------------
__global__ __launch_bounds__(256) void qk_rope_kernel(
    const float* __restrict__ qkv,
    const float* __restrict__ qw, const float* __restrict__ kw,
    float* __restrict__ qo, float* __restrict__ ko, float* __restrict__ vo)
{
    __shared__ float qn[DD];
    __shared__ float kn[DD];
    __shared__ float red[20];
    int row = blockIdx.x;          // b*L + l
    int b = row / LL;
    int l = row % LL;
    int t = threadIdx.x;
    const float* qr = qkv + (size_t)row * (3*DD);
    const float* kr = qr + DD;
    const float* vr = qr + 2*DD;

    float4 qv = ((const float4*)qr)[t];
    float4 kv = ((const float4*)kr)[t];

    float s  = qv.x + qv.y + qv.z + qv.w;
    float s2 = qv.x*qv.x + qv.y*qv.y + qv.z*qv.z + qv.w*qv.w;
    block_reduce2(s, s2, red);
    float qmu = s * (1.0f/DD);
    float qinv = rsqrtf(s2 * (1.0f/DD) - qmu*qmu + EPS);
    float u  = kv.x + kv.y + kv.z + kv.w;
    float u2 = kv.x*kv.x + kv.y*kv.y + kv.z*kv.z + kv.w*kv.w;
    block_reduce2(u, u2, red);
    float kmu = u * (1.0f/DD);
    float kinv = rsqrtf(u2 * (1.0f/DD) - kmu*kmu + EPS);

    float4 qwv = ((const float4*)qw)[t];
    float4 kwv = ((const float4*)kw)[t];
    int d0 = 4 * t;
    qn[d0+0] = (qv.x - qmu)*qinv*qwv.x;
    qn[d0+1] = (qv.y - qmu)*qinv*qwv.y;
    qn[d0+2] = (qv.z - qmu)*qinv*qwv.z;
    qn[d0+3] = (qv.w - qmu)*qinv*qwv.w;
    kn[d0+0] = (kv.x - kmu)*kinv*kwv.x;
    kn[d0+1] = (kv.y - kmu)*kinv*kwv.y;
    kn[d0+2] = (kv.z - kmu)*kinv*kwv.z;
    kn[d0+3] = (kv.w - kmu)*kinv*kwv.w;
    __syncthreads();

#pragma unroll
    for (int e = 0; e < 4; e++) {
        int dd = d0 + e;
        int h  = dd >> 6;
        int j  = dd & 63;
        int jj = j & 31;
        float inv_freq = __powf(10000.0f, -(float)(2*jj) * (1.0f/64.0f));
        float ang = (float)l * inv_freq;
        float sn, cs;
        sincosf(ang, &sn, &cs);
        int pd = (j < 32) ? dd + 32 : dd - 32;
        float qvv = qn[dd], qp = qn[pd];
        float kvv = kn[dd], kp = kn[pd];
        float rq = (j < 32) ? (qvv*cs - qp*sn) : (qvv*cs + qp*sn);
        float rk = (j < 32) ? (kvv*cs - kp*sn) : (kvv*cs + kp*sn);
        size_t oidx = ((size_t)(b*HH + h) * LL + l) * DHD + j;
        qo[oidx] = rq;
        ko[oidx] = rk;
        vo[oidx] = vr[dd];
    }
}

// ---------------- flash attention with seq_id block-diagonal skip ----------------
#define ATT_SMEM_FLOATS (4096 + 4160 + 4096 + 128)
__global__ __launch_bounds__(256) void attn_kernel(
    const float* __restrict__ Q, const float* __restrict__ K,
    const float* __restrict__ V, const int* __restrict__ seq_id,
    __nv_bfloat16* __restrict__ ctxh, __nv_bfloat16* __restrict__ ctxl)
{
    extern __shared__ float sm[];
    float* Qt = sm;
    float* Kt = sm + 4096;
    float* Ps = Kt;
    float* Vs = sm + 4096 + 4160;
    int* seqq = (int*)(sm + 4096 + 4160 + 4096);
    int* seqk = seqq + 64;

    int t  = threadIdx.x;
    int ty = t >> 4;
    int tx = t & 15;
    int q0 = blockIdx.x * 64;
    int bh = blockIdx.y;
    int b  = bh >> 4;
    int h  = bh & 15;

    const float* Qg = Q + ((size_t)bh * LL + q0) * DHD;
    const int* seqb = seq_id + (size_t)b * LL;

#pragma unroll
    for (int i = 0; i < 4; i++) {
        int idx = t + i * 256;
        int r  = idx >> 4;
        int jv = idx & 15;
        float4 q4 = *(const float4*)(Qg + r*DHD + 4*jv);
        Qt[(4*jv+0)*64 + r] = q4.x;
        Qt[(4*jv+1)*64 + r] = q4.y;
        Qt[(4*jv+2)*64 + r] = q4.z;
        Qt[(4*jv+3)*64 + r] = q4.w;
    }
    if (t < 64) seqq[t] = seqb[q0 + t];
    __syncthreads();

    int qmin = seqq[0], qmax = seqq[63];
    int sq[4];
#pragma unroll
    for (int i = 0; i < 4; i++) sq[i] = seqq[4*ty + i];

    float m[4], lsum[4], acc[4][4];
#pragma unroll
    for (int i = 0; i < 4; i++) {
        m[i] = -1e30f; lsum[i] = 0.f;
#pragma unroll
        for (int j = 0; j < 4; j++) acc[i][j] = 0.f;
    }
    const float scale = 0.125f;

    for (int kt = 0; kt < LL/64; kt++) {
        int k0 = kt * 64;
        int kmin = seqb[k0], kmax = seqb[k0 + 63];
        if (kmax < qmin || kmin > qmax) continue;

        __syncthreads();
        const float* Kg = K + ((size_t)bh * LL + k0) * DHD;
        const float* Vg = V + ((size_t)bh * LL + k0) * DHD;
#pragma unroll
        for (int i = 0; i < 4; i++) {
            int idx = t + i * 256;
            int c  = idx >> 4;
            int jv = idx & 15;
            float4 k4 = *(const float4*)(Kg + c*DHD + 4*jv);
            Kt[(4*jv+0)*64 + c] = k4.x;
            Kt[(4*jv+1)*64 + c] = k4.y;
            Kt[(4*jv+2)*64 + c] = k4.z;
            Kt[(4*jv+3)*64 + c] = k4.w;
            *(float4*)(Vs + c*64 + 4*jv) = *(const float4*)(Vg + c*DHD + 4*jv);
        }
        if (t < 64) seqk[t] = seqb[k0 + t];
        __syncthreads();

        float s[4][4];
#pragma unroll
        for (int i = 0; i < 4; i++)
#pragma unroll
            for (int j = 0; j < 4; j++) s[i][j] = 0.f;
#pragma unroll 8
        for (int k = 0; k < 64; k++) {
            float4 qv = *(const float4*)&Qt[k*64 + 4*ty];
            float4 kv = *(const float4*)&Kt[k*64 + 4*tx];
            float qa[4] = {qv.x,qv.y,qv.z,qv.w};
            float ka[4] = {kv.x,kv.y,kv.z,kv.w};
#pragma unroll
            for (int i = 0; i < 4; i++)
#pragma unroll
                for (int j = 0; j < 4; j++)
                    s[i][j] += qa[i] * ka[j];
        }

        int sk[4];
#pragma unroll
        for (int j = 0; j < 4; j++) sk[j] = seqk[4*tx + j];

        bool ok[4][4];
#pragma unroll
        for (int i = 0; i < 4; i++)
#pragma unroll
            for (int j = 0; j < 4; j++) {
                ok[i][j] = (sq[i] == sk[j]);
                s[i][j] = ok[i][j] ? s[i][j]*scale : -1e30f;
            }

        float p[4][4];
#pragma unroll
        for (int i = 0; i < 4; i++) {
            float rm = fmaxf(fmaxf(s[i][0], s[i][1]), fmaxf(s[i][2], s[i][3]));
#pragma unroll
            for (int o = 1; o <= 8; o <<= 1)
                rm = fmaxf(rm, __shfl_xor_sync(0xffffffffu, rm, o));
            float mn = fmaxf(m[i], rm);
            float corr = __expf(m[i] - mn);
            float rs = 0.f;
#pragma unroll
            for (int j = 0; j < 4; j++) {
                p[i][j] = ok[i][j] ? __expf(s[i][j] - mn) : 0.f;
                rs += p[i][j];
            }
#pragma unroll
            for (int o = 1; o <= 8; o <<= 1)
                rs += __shfl_xor_sync(0xffffffffu, rs, o);
            lsum[i] = lsum[i] * corr + rs;
#pragma unroll
            for (int j = 0; j < 4; j++) acc[i][j] *= corr;
            m[i] = mn;
        }

        __syncthreads();
#pragma unroll
        for (int i = 0; i < 4; i++)
#pragma unroll
            for (int j = 0; j < 4; j++)
                Ps[(4*ty+i)*65 + 4*tx + j] = p[i][j];
        __syncthreads();

#pragma unroll 8
        for (int c = 0; c < 64; c++) {
            float4 vv = *(const float4*)&Vs[c*64 + 4*tx];
#pragma unroll
            for (int i = 0; i < 4; i++) {
                float pi = Ps[(4*ty+i)*65 + c];
                acc[i][0] += pi * vv.x;
                acc[i][1] += pi * vv.y;
                acc[i][2] += pi * vv.z;
                acc[i][3] += pi * vv.w;
            }
        }
    }

#pragma unroll
    for (int i = 0; i < 4; i++) {
        float invl = 1.0f / lsum[i];
        float o0 = acc[i][0]*invl, o1 = acc[i][1]*invl;
        float o2 = acc[i][2]*invl, o3 = acc[i][3]*invl;
        __nv_bfloat16 h0 = __float2bfloat16(o0), h1 = __float2bfloat16(o1);
        __nv_bfloat16 h2 = __float2bfloat16(o2), h3 = __float2bfloat16(o3);
        uint2 hp = make_uint2(pack_bf2(o0, o1), pack_bf2(o2, o3));
        uint2 lp = make_uint2(
            pack_bf2(o0 - __bfloat162float(h0), o1 - __bfloat162float(h1)),
            pack_bf2(o2 - __bfloat162float(h2), o3 - __bfloat162float(h3)));
        size_t oidx = (((size_t)b*LL + q0 + 4*ty + i) * HH + h) * DHD + 4*tx;
        *(uint2*)(ctxh + oidx) = hp;
        *(uint2*)(ctxl + oidx) = lp;
    }
}

// ---------------- launch ----------------
extern "C" void kernel_launch(void* const* d_in, const int* in_sizes, int n_in,
                              void* d_out, int out_size)
{
    const float* x     = (const float*)d_in[0];
    const int*   seq   = (const int*)  d_in[1];
    const float* ln1w  = (const float*)d_in[2];
    const float* ln1b  = (const float*)d_in[3];
    const float* wqkv  = (const float*)d_in[4];
    const float* qlnw  = (const float*)d_in[5];
    const float* klnw  = (const float*)d_in[6];
    const float* outw  = (const float*)d_in[7];
    float* out = (float*)d_out;

    float *qkv, *q, *k, *v;
    __nv_bfloat16 *hh, *hl, *wqh, *wql, *ctxh, *ctxl, *owh, *owl;
    cudaGetSymbolAddress((void**)&qkv,  g_qkv);
    cudaGetSymbolAddress((void**)&q,    g_q);
    cudaGetSymbolAddress((void**)&k,    g_k);
    cudaGetSymbolAddress((void**)&v,    g_v);
    cudaGetSymbolAddress((void**)&hh,   g_hh);
    cudaGetSymbolAddress((void**)&hl,   g_hl);
    cudaGetSymbolAddress((void**)&wqh,  g_wqh);
    cudaGetSymbolAddress((void**)&wql,  g_wql);
    cudaGetSymbolAddress((void**)&ctxh, g_ctxh);
    cudaGetSymbolAddress((void**)&ctxl, g_ctxl);
    cudaGetSymbolAddress((void**)&owh,  g_owh);
    cudaGetSymbolAddress((void**)&owl,  g_owl);

    cudaFuncSetAttribute(attn_kernel, cudaFuncAttributeMaxDynamicSharedMemorySize,
                         ATT_SMEM_FLOATS * 4);
    cudaFuncSetAttribute(gemm_bf16s, cudaFuncAttributeMaxDynamicSharedMemorySize,
                         GEMM_SMEM);

    ln1_split_kernel<<<ROWS, 256>>>(x, ln1w, ln1b, hh, hl);
    split_kernel<<<3*DD*DD/1024, 256>>>(wqkv, wqh, wql);
    gemm_bf16s<<<dim3(3*DD/128, ROWS/128), 256, GEMM_SMEM>>>(
        hh, hl, wqh, wql, qkv, ROWS, 3*DD, DD);
    qk_rope_kernel<<<ROWS, 256>>>(qkv, qlnw, klnw, q, k, v);
    attn_kernel<<<dim3(LL/64, BB*HH), 256, ATT_SMEM_FLOATS*4>>>(q, k, v, seq, ctxh, ctxl);
    split_kernel<<<DD*DD/1024, 256>>>(outw, owh, owl);
    gemm_bf16s<<<dim3(DD/128, ROWS/128), 256, GEMM_SMEM>>>(
        ctxh, ctxl, owh, owl, out, ROWS, DD, DD);
}

// round 6
// speedup vs baseline: 4.7823x; 1.3996x over previous
#include <cuda_runtime.h>
#include <cuda_bf16.h>
#include <math.h>
#include <stdint.h>

// Problem constants
#define BB 2
#define LL 2048
#define DD 1024
#define HH 16
#define DHD 64
#define ROWS (BB*LL)        // 4096
#define EPS 1e-5f

// ---------------- scratch (device globals; no allocation) ----------------
__device__ float g_qkv[ROWS * 3 * DD];            // 48 MB
__device__ float g_v[BB * HH * LL * DHD];         // 16 MB [BH][L][DH] fp32
__device__ __nv_bfloat16 g_qh[BB*HH*LL*DHD];      // 8 MB [BH][L][DH]
__device__ __nv_bfloat16 g_ql[BB*HH*LL*DHD];
__device__ __nv_bfloat16 g_kh[BB*HH*LL*DHD];
__device__ __nv_bfloat16 g_kl[BB*HH*LL*DHD];
__device__ __nv_bfloat16 g_vth[BB*HH*DHD*LL];     // 8 MB [BH][DH][L]
__device__ __nv_bfloat16 g_vtl[BB*HH*DHD*LL];
__device__ __nv_bfloat16 g_hh[ROWS * DD];
__device__ __nv_bfloat16 g_hl[ROWS * DD];
__device__ __nv_bfloat16 g_wqh[3 * DD * DD];
__device__ __nv_bfloat16 g_wql[3 * DD * DD];
__device__ __nv_bfloat16 g_ctxh[ROWS * DD];
__device__ __nv_bfloat16 g_ctxl[ROWS * DD];
__device__ __nv_bfloat16 g_owh[DD * DD];
__device__ __nv_bfloat16 g_owl[DD * DD];

// =================== helpers ===================
__device__ __forceinline__ uint32_t smem_u32(const void* p) {
    uint32_t a;
    asm("{ .reg .u64 t; cvta.to.shared.u64 t, %1; cvt.u32.u64 %0, t; }" : "=r"(a) : "l"(p));
    return a;
}
__device__ __forceinline__ uint32_t pack_bf2(float x, float y) {
    __nv_bfloat162 v = __floats2bfloat162_rn(x, y);
    return *(uint32_t*)&v;
}
__device__ __forceinline__ void cpasync16(uint32_t dst, const void* src) {
    asm volatile("cp.async.cg.shared.global [%0], [%1], 16;" :: "r"(dst), "l"(src));
}
__device__ __forceinline__ void ldsm4(uint32_t* r, uint32_t addr) {
    asm volatile("ldmatrix.sync.aligned.m8n8.x4.shared.b16 {%0,%1,%2,%3}, [%4];"
        : "=r"(r[0]), "=r"(r[1]), "=r"(r[2]), "=r"(r[3]) : "r"(addr));
}
__device__ __forceinline__ void ldsm2(uint32_t* r, uint32_t addr) {
    asm volatile("ldmatrix.sync.aligned.m8n8.x2.shared.b16 {%0,%1}, [%2];"
        : "=r"(r[0]), "=r"(r[1]) : "r"(addr));
}
__device__ __forceinline__ void mma16816(float* d, const uint32_t* a, const uint32_t* b) {
    asm volatile(
        "mma.sync.aligned.m16n8k16.row.col.f32.bf16.bf16.f32 "
        "{%0,%1,%2,%3}, {%4,%5,%6,%7}, {%8,%9}, {%0,%1,%2,%3};"
        : "+f"(d[0]), "+f"(d[1]), "+f"(d[2]), "+f"(d[3])
        : "r"(a[0]), "r"(a[1]), "r"(a[2]), "r"(a[3]), "r"(b[0]), "r"(b[1]));
}

// =================== split-bf16 NT GEMM via mma.sync (from R5, unchanged) ===================
#define GSTAGE_BYTES 65536
#define GEMM_SMEM (3 * GSTAGE_BYTES)

__device__ __forceinline__ void load_stage(
    uint32_t sbase,
    const __nv_bfloat16* __restrict__ Ah, const __nv_bfloat16* __restrict__ Al,
    const __nv_bfloat16* __restrict__ Bh, const __nv_bfloat16* __restrict__ Bl,
    int m0, int n0, int K, int k0, int t)
{
#pragma unroll
    for (int i = 0; i < 4; i++) {
        int chunk = t + i * 256;
        int row = chunk >> 3;
        int c16 = chunk & 7;
        uint32_t soff = (uint32_t)(row << 7) + (uint32_t)((c16 << 4) ^ ((row & 7) << 4));
        size_t ga = (size_t)(m0 + row) * K + k0 + c16 * 8;
        size_t gb = (size_t)(n0 + row) * K + k0 + c16 * 8;
        cpasync16(sbase + soff,         Ah + ga);
        cpasync16(sbase + 16384 + soff, Al + ga);
        cpasync16(sbase + 32768 + soff, Bh + gb);
        cpasync16(sbase + 49152 + soff, Bl + gb);
    }
}

__global__ __launch_bounds__(256, 1) void gemm_bf16s(
    const __nv_bfloat16* __restrict__ Ah, const __nv_bfloat16* __restrict__ Al,
    const __nv_bfloat16* __restrict__ Bh, const __nv_bfloat16* __restrict__ Bl,
    float* __restrict__ C, int M, int N, int K)
{
    extern __shared__ char dsm[];
    uint32_t sb = smem_u32(dsm);
    int t = threadIdx.x;
    int lane = t & 31, wid = t >> 5;
    int m0 = blockIdx.y * 128, n0 = blockIdx.x * 128;
    int wm = (wid >> 1) * 32;
    int wn = (wid & 1) * 64;

    float acc[2][8][4];
#pragma unroll
    for (int a = 0; a < 2; a++)
#pragma unroll
        for (int b = 0; b < 8; b++)
#pragma unroll
            for (int c = 0; c < 4; c++) acc[a][b][c] = 0.f;

    const int NC = K / 64;
    load_stage(sb + 0 * GSTAGE_BYTES, Ah, Al, Bh, Bl, m0, n0, K, 0, t);
    asm volatile("cp.async.commit_group;" ::: "memory");
    load_stage(sb + 1 * GSTAGE_BYTES, Ah, Al, Bh, Bl, m0, n0, K, 64, t);
    asm volatile("cp.async.commit_group;" ::: "memory");

    int arow = wm + (lane & 15);
    uint32_t axor = (uint32_t)((lane & 7) << 4);
    uint32_t ah16 = (uint32_t)((lane >> 4) << 4);
    int brow = wn + (lane & 7);
    uint32_t bh16 = (uint32_t)(((lane >> 3) & 1) << 4);

    for (int kc = 0; kc < NC; kc++) {
        int ls = kc + 2;
        if (ls < NC)
            load_stage(sb + (ls % 3) * GSTAGE_BYTES, Ah, Al, Bh, Bl, m0, n0, K, ls * 64, t);
        asm volatile("cp.async.commit_group;" ::: "memory");
        asm volatile("cp.async.wait_group 2;" ::: "memory");
        __syncthreads();

        uint32_t st = sb + (kc % 3) * GSTAGE_BYTES;
#pragma unroll
        for (int ks = 0; ks < 4; ks++) {
            uint32_t ksB = (uint32_t)(ks * 32);
            uint32_t ahf[2][4], alf[2][4];
#pragma unroll
            for (int mt = 0; mt < 2; mt++) {
                uint32_t ra = st + (uint32_t)((arow + mt * 16) << 7) + ((ksB + ah16) ^ axor);
                ldsm4(ahf[mt], ra);
                ldsm4(alf[mt], ra + 16384);
            }
            uint32_t bhf[8][2], blf[8][2];
#pragma unroll
            for (int nt = 0; nt < 8; nt++) {
                uint32_t rb = st + 32768 + (uint32_t)((brow + nt * 8) << 7) + ((ksB + bh16) ^ axor);
                ldsm2(bhf[nt], rb);
                ldsm2(blf[nt], rb + 16384);
            }
#pragma unroll
            for (int mt = 0; mt < 2; mt++)
#pragma unroll
                for (int nt = 0; nt < 8; nt++)
                    mma16816(acc[mt][nt], ahf[mt], bhf[nt]);
#pragma unroll
            for (int mt = 0; mt < 2; mt++)
#pragma unroll
                for (int nt = 0; nt < 8; nt++)
                    mma16816(acc[mt][nt], ahf[mt], blf[nt]);
#pragma unroll
            for (int mt = 0; mt < 2; mt++)
#pragma unroll
                for (int nt = 0; nt < 8; nt++)
                    mma16816(acc[mt][nt], alf[mt], bhf[nt]);
        }
        __syncthreads();
    }

    int crow = lane >> 2;
    int ccol = (lane & 3) * 2;
#pragma unroll
    for (int mt = 0; mt < 2; mt++)
#pragma unroll
        for (int nt = 0; nt < 8; nt++) {
            int col = n0 + wn + nt * 8 + ccol;
            float* p0 = C + (size_t)(m0 + wm + mt * 16 + crow) * N + col;
            float* p1 = C + (size_t)(m0 + wm + mt * 16 + crow + 8) * N + col;
            float2 v0 = { acc[mt][nt][0], acc[mt][nt][1] };
            float2 v1 = { acc[mt][nt][2], acc[mt][nt][3] };
            *(float2*)p0 = v0;
            *(float2*)p1 = v1;
        }
}

// ---------------- generic fp32 -> bf16 hi/lo split ----------------
__global__ __launch_bounds__(256) void split_kernel(
    const float* __restrict__ in, __nv_bfloat16* __restrict__ hi,
    __nv_bfloat16* __restrict__ lo)
{
    int i = (blockIdx.x * 256 + threadIdx.x) * 4;
    float4 v = *(const float4*)(in + i);
    __nv_bfloat16 hx = __float2bfloat16(v.x), hy = __float2bfloat16(v.y);
    __nv_bfloat16 hz = __float2bfloat16(v.z), hw = __float2bfloat16(v.w);
    uint2 hp = make_uint2(pack_bf2(v.x, v.y), pack_bf2(v.z, v.w));
    uint2 lp = make_uint2(
        pack_bf2(v.x - __bfloat162float(hx), v.y - __bfloat162float(hy)),
        pack_bf2(v.z - __bfloat162float(hz), v.w - __bfloat162float(hw)));
    *(uint2*)(hi + i) = hp;
    *(uint2*)(lo + i) = lp;
}

// ---------------- block reduce ----------------
__device__ __forceinline__ void block_reduce2(float& a, float& b, float* red) {
    int lane = threadIdx.x & 31;
    int w    = threadIdx.x >> 5;
#pragma unroll
    for (int o = 16; o > 0; o >>= 1) {
        a += __shfl_xor_sync(0xffffffffu, a, o);
        b += __shfl_xor_sync(0xffffffffu, b, o);
    }
    if (lane == 0) { red[w] = a; red[8 + w] = b; }
    __syncthreads();
    if (threadIdx.x == 0) {
        float sa = 0.f, sb = 0.f;
#pragma unroll
        for (int i = 0; i < 8; i++) { sa += red[i]; sb += red[8 + i]; }
        red[16] = sa; red[17] = sb;
    }
    __syncthreads();
    a = red[16]; b = red[17];
    __syncthreads();
}

// ---------------- LN1 with fused bf16 hi/lo split output ----------------
__global__ __launch_bounds__(256) void ln1_split_kernel(
    const float* __restrict__ x, const float* __restrict__ w,
    const float* __restrict__ bias,
    __nv_bfloat16* __restrict__ hh, __nv_bfloat16* __restrict__ hl)
{
    __shared__ float red[20];
    int row = blockIdx.x;
    const float4* xr = (const float4*)(x + (size_t)row * DD);
    float4 v = xr[threadIdx.x];
    float s  = v.x + v.y + v.z + v.w;
    float s2 = v.x*v.x + v.y*v.y + v.z*v.z + v.w*v.w;
    block_reduce2(s, s2, red);
    float mu  = s * (1.0f / DD);
    float var = s2 * (1.0f / DD) - mu * mu;
    float inv = rsqrtf(var + EPS);
    const float4* w4 = (const float4*)w;
    const float4* b4 = (const float4*)bias;
    float4 ww = w4[threadIdx.x], bb2 = b4[threadIdx.x];
    float4 o;
    o.x = (v.x - mu) * inv * ww.x + bb2.x;
    o.y = (v.y - mu) * inv * ww.y + bb2.y;
    o.z = (v.z - mu) * inv * ww.z + bb2.z;
    o.w = (v.w - mu) * inv * ww.w + bb2.w;
    __nv_bfloat16 hx = __float2bfloat16(o.x), hy = __float2bfloat16(o.y);
    __nv_bfloat16 hz = __float2bfloat16(o.z), hw = __float2bfloat16(o.w);
    uint2 hp = make_uint2(pack_bf2(o.x, o.y), pack_bf2(o.z, o.w));
    uint2 lp = make_uint2(
        pack_bf2(o.x - __bfloat162float(hx), o.y - __bfloat162float(hy)),
        pack_bf2(o.z - __bfloat162float(hz), o.w - __bfloat162float(hw)));
    size_t off = (size_t)row * DD + threadIdx.x * 4;
    *(uint2*)(hh + off) = hp;
    *(uint2*)(hl + off) = lp;
}

// ---------------- Q/K LN + RoPE + split to bf16 hi/lo; V fp32 scatter ----------------
// q is pre-scaled by 1/sqrt(DH)=0.125 (folded into attention scores).
__global__ __launch_bounds__(256) void qk_rope_kernel(
    const float* __restrict__ qkv,
    const float* __restrict__ qw, const float* __restrict__ kw,
    __nv_bfloat16* __restrict__ qh, __nv_bfloat16* __restrict__ ql,
    __nv_bfloat16* __restrict__ kh, __nv_bfloat16* __restrict__ kl,
    float* __restrict__ vo)
{
    __shared__ float qn[DD];
    __shared__ float kn[DD];
    __shared__ float red[20];
    int row = blockIdx.x;          // b*L + l
    int b = row / LL;
    int l = row % LL;
    int t = threadIdx.x;
    const float* qr = qkv + (size_t)row * (3*DD);
    const float* kr = qr + DD;
    const float* vr = qr + 2*DD;

    float4 qv = ((const float4*)qr)[t];
    float4 kv = ((const float4*)kr)[t];

    float s  = qv.x + qv.y + qv.z + qv.w;
    float s2 = qv.x*qv.x + qv.y*qv.y + qv.z*qv.z + qv.w*qv.w;
    block_reduce2(s, s2, red);
    float qmu = s * (1.0f/DD);
    float qinv = rsqrtf(s2 * (1.0f/DD) - qmu*qmu + EPS);
    float u  = kv.x + kv.y + kv.z + kv.w;
    float u2 = kv.x*kv.x + kv.y*kv.y + kv.z*kv.z + kv.w*kv.w;
    block_reduce2(u, u2, red);
    float kmu = u * (1.0f/DD);
    float kinv = rsqrtf(u2 * (1.0f/DD) - kmu*kmu + EPS);

    float4 qwv = ((const float4*)qw)[t];
    float4 kwv = ((const float4*)kw)[t];
    int d0 = 4 * t;
    qn[d0+0] = (qv.x - qmu)*qinv*qwv.x;
    qn[d0+1] = (qv.y - qmu)*qinv*qwv.y;
    qn[d0+2] = (qv.z - qmu)*qinv*qwv.z;
    qn[d0+3] = (qv.w - qmu)*qinv*qwv.w;
    kn[d0+0] = (kv.x - kmu)*kinv*kwv.x;
    kn[d0+1] = (kv.y - kmu)*kinv*kwv.y;
    kn[d0+2] = (kv.z - kmu)*kinv*kwv.z;
    kn[d0+3] = (kv.w - kmu)*kinv*kwv.w;
    __syncthreads();

    float rq[4], rk[4];
#pragma unroll
    for (int e = 0; e < 4; e++) {
        int dd = d0 + e;
        int j  = dd & 63;
        int jj = j & 31;
        float inv_freq = __powf(10000.0f, -(float)(2*jj) * (1.0f/64.0f));
        float ang = (float)l * inv_freq;
        float sn, cs;
        sincosf(ang, &sn, &cs);
        int pd = (j < 32) ? dd + 32 : dd - 32;
        float qvv = qn[dd], qp = qn[pd];
        float kvv = kn[dd], kp = kn[pd];
        rq[e] = ((j < 32) ? (qvv*cs - qp*sn) : (qvv*cs + qp*sn)) * 0.125f;
        rk[e] = (j < 32) ? (kvv*cs - kp*sn) : (kvv*cs + kp*sn);
    }
    int hidx = d0 >> 6;
    int j0 = d0 & 63;
    size_t base = ((size_t)(b*HH + hidx) * LL + l) * DHD + j0;

    uint2 qhp = make_uint2(pack_bf2(rq[0], rq[1]), pack_bf2(rq[2], rq[3]));
    uint2 khp = make_uint2(pack_bf2(rk[0], rk[1]), pack_bf2(rk[2], rk[3]));
    float rql[4], rkl[4];
#pragma unroll
    for (int e = 0; e < 4; e++) {
        rql[e] = rq[e] - __bfloat162float(__float2bfloat16(rq[e]));
        rkl[e] = rk[e] - __bfloat162float(__float2bfloat16(rk[e]));
    }
    uint2 qlp = make_uint2(pack_bf2(rql[0], rql[1]), pack_bf2(rql[2], rql[3]));
    uint2 klp = make_uint2(pack_bf2(rkl[0], rkl[1]), pack_bf2(rkl[2], rkl[3]));
    *(uint2*)(qh + base) = qhp;
    *(uint2*)(ql + base) = qlp;
    *(uint2*)(kh + base) = khp;
    *(uint2*)(kl + base) = klp;
    float4 vv = { vr[d0], vr[d0+1], vr[d0+2], vr[d0+3] };
    *(float4*)(vo + base) = vv;
}

// ---------------- V transpose + split: [BH][L][DH] fp32 -> [BH][DH][L] bf16 hi/lo ----------------
__global__ __launch_bounds__(256) void v_trans_kernel(
    const float* __restrict__ v, __nv_bfloat16* __restrict__ vth,
    __nv_bfloat16* __restrict__ vtl)
{
    __shared__ float vs[64][65];
    int k0 = blockIdx.x * 64;
    int bh = blockIdx.y;
    int t = threadIdx.x;
#pragma unroll
    for (int i = 0; i < 4; i++) {
        int idx = t + i * 256;
        int r = idx >> 4;
        int c = (idx & 15) * 4;
        float4 x = *(const float4*)(v + ((size_t)bh * LL + k0 + r) * DHD + c);
        vs[r][c+0] = x.x; vs[r][c+1] = x.y; vs[r][c+2] = x.z; vs[r][c+3] = x.w;
    }
    __syncthreads();
    int d = t >> 2;
#pragma unroll
    for (int j = 0; j < 8; j++) {
        int kp = (t & 3) * 2 + j * 8;
        float f0 = vs[kp][d], f1 = vs[kp+1][d];
        __nv_bfloat16 h0 = __float2bfloat16(f0), h1 = __float2bfloat16(f1);
        size_t o = ((size_t)bh * DHD + d) * LL + k0 + kp;
        *(uint32_t*)(vth + o) = pack_bf2(f0, f1);
        *(uint32_t*)(vtl + o) = pack_bf2(f0 - __bfloat162float(h0), f1 - __bfloat162float(h1));
    }
}

// =================== tensor-core flash attention (split bf16) ===================
// block: 128 q-rows x one (b,h). 8 warps, each m16. k-tiles of 64 with seq-id skip.
#define AQ_H 0
#define AQ_L 16384
#define AST0 32768
#define ASTG 33024          // Kh 8K | Kl 8K | Vth 8K | Vtl 8K | seqk 256B
#define ASEQQ (AST0 + 2*ASTG)      // 98816
#define ALIST (ASEQQ + 512)        // 99328: [0]=count, [1..32]=tiles
#define ATT_SMEM (ALIST + 256)     // 99584

__device__ __forceinline__ void att_prefetch(
    uint32_t stb,
    const __nv_bfloat16* __restrict__ Kh, const __nv_bfloat16* __restrict__ Kl,
    const __nv_bfloat16* __restrict__ Vth, const __nv_bfloat16* __restrict__ Vtl,
    const int* __restrict__ seqb, int bh, int k0, int t)
{
#pragma unroll
    for (int i = 0; i < 2; i++) {
        int idx = t + i * 256;      // 0..511
        int row = idx >> 3;         // 0..63
        int c16 = idx & 7;
        uint32_t soff = (uint32_t)(row << 7) + (uint32_t)((c16 << 4) ^ ((row & 7) << 4));
        size_t gk = ((size_t)bh * LL + k0 + row) * DHD + c16 * 8;
        size_t gv = ((size_t)bh * DHD + row) * LL + k0 + c16 * 8;
        cpasync16(stb + soff,          Kh + gk);
        cpasync16(stb + 8192 + soff,   Kl + gk);
        cpasync16(stb + 16384 + soff,  Vth + gv);
        cpasync16(stb + 24576 + soff,  Vtl + gv);
    }
    if (t < 16) cpasync16(stb + 32768 + t * 16, seqb + k0 + t * 4);
}

__global__ __launch_bounds__(256, 1) void attn_mma(
    const __nv_bfloat16* __restrict__ Qh, const __nv_bfloat16* __restrict__ Ql,
    const __nv_bfloat16* __restrict__ Kh, const __nv_bfloat16* __restrict__ Kl,
    const __nv_bfloat16* __restrict__ Vth, const __nv_bfloat16* __restrict__ Vtl,
    const int* __restrict__ seq_id,
    __nv_bfloat16* __restrict__ ctxh, __nv_bfloat16* __restrict__ ctxl)
{
    extern __shared__ char sm[];
    uint32_t sb = smem_u32(sm);
    int t = threadIdx.x, lane = t & 31, wid = t >> 5;
    int q0 = blockIdx.x * 128;
    int bh = blockIdx.y;
    int b = bh >> 4, h = bh & 15;
    const int* seqb = seq_id + (size_t)b * LL;
    int* seqq = (int*)(sm + ASEQQ);
    int* list = (int*)(sm + ALIST);

    // Q tiles -> smem (group 0)
#pragma unroll
    for (int i = 0; i < 4; i++) {
        int idx = t + i * 256;
        int row = idx >> 3;
        int c16 = idx & 7;
        uint32_t soff = (uint32_t)(row << 7) + (uint32_t)((c16 << 4) ^ ((row & 7) << 4));
        size_t g = ((size_t)bh * LL + q0 + row) * DHD + c16 * 8;
        cpasync16(sb + AQ_H + soff, Qh + g);
        cpasync16(sb + AQ_L + soff, Ql + g);
    }
    asm volatile("cp.async.commit_group;" ::: "memory");
    if (t < 128) seqq[t] = seqb[q0 + t];

    // visited tile list (warp 0, 32 tiles = 32 lanes)
    if (wid == 0) {
        int qmin = seqb[q0], qmax = seqb[q0 + 127];
        int k0 = lane * 64;
        bool vis = (seqb[k0] <= qmax) && (seqb[k0 + 63] >= qmin);
        uint32_t bal = __ballot_sync(0xffffffffu, vis);
        int pos = __popc(bal & ((1u << lane) - 1u));
        if (vis) list[1 + pos] = lane;
        if (lane == 0) list[0] = __popc(bal);
    }
    __syncthreads();
    int nv = list[0];

    // prefetch stage 0 (group 1)
    att_prefetch(sb + AST0, Kh, Kl, Vth, Vtl, seqb, bh, list[1] * 64, t);
    asm volatile("cp.async.commit_group;" ::: "memory");
    asm volatile("cp.async.wait_group 1;" ::: "memory");   // Q resident
    __syncthreads();

    // Q fragments (resident in registers)
    uint32_t qfh[4][4], qfl[4][4];
    {
        int arow = wid * 16 + (lane & 15);
        uint32_t axor = (uint32_t)((lane & 7) << 4);
        uint32_t ah16 = (uint32_t)((lane >> 4) << 4);
#pragma unroll
        for (int ks = 0; ks < 4; ks++) {
            uint32_t ra = sb + AQ_H + (uint32_t)(arow << 7) + (((uint32_t)(ks * 32) + ah16) ^ axor);
            ldsm4(qfh[ks], ra);
            ldsm4(qfl[ks], ra + 16384);
        }
    }

    int r0 = wid * 16 + (lane >> 2);
    int sq0 = seqq[r0], sq1 = seqq[r0 + 8];
    float m0 = -1e30f, m1 = -1e30f, l0 = 0.f, l1 = 0.f;
    float oacc[8][4];
#pragma unroll
    for (int nt = 0; nt < 8; nt++)
#pragma unroll
        for (int c = 0; c < 4; c++) oacc[nt][c] = 0.f;

    uint32_t bxor = (uint32_t)((lane & 7) << 4);
    uint32_t bh16 = (uint32_t)(((lane >> 3) & 1) << 4);
    int brl = lane & 7;

    for (int vi = 0; vi < nv; vi++) {
        uint32_t stb = sb + AST0 + (uint32_t)((vi & 1) * ASTG);
        if (vi + 1 < nv)
            att_prefetch(sb + AST0 + (uint32_t)(((vi + 1) & 1) * ASTG),
                         Kh, Kl, Vth, Vtl, seqb, bh, list[2 + vi] * 64, t);
        asm volatile("cp.async.commit_group;" ::: "memory");
        asm volatile("cp.async.wait_group 1;" ::: "memory");
        __syncthreads();

        int* seqk = (int*)(sm + AST0 + (vi & 1) * ASTG + 32768);

        // S = Q K^T  (3-term split)
        float sacc[8][4];
#pragma unroll
        for (int nt = 0; nt < 8; nt++)
#pragma unroll
            for (int c = 0; c < 4; c++) sacc[nt][c] = 0.f;
#pragma unroll
        for (int ks = 0; ks < 4; ks++) {
            uint32_t khf[8][2], klf[8][2];
#pragma unroll
            for (int nt = 0; nt < 8; nt++) {
                uint32_t rb = stb + (uint32_t)((nt * 8 + brl) << 7)
                            + (((uint32_t)(ks * 32) + bh16) ^ bxor);
                ldsm2(khf[nt], rb);
                ldsm2(klf[nt], rb + 8192);
            }
#pragma unroll
            for (int nt = 0; nt < 8; nt++) mma16816(sacc[nt], qfh[ks], khf[nt]);
#pragma unroll
            for (int nt = 0; nt < 8; nt++) mma16816(sacc[nt], qfh[ks], klf[nt]);
#pragma unroll
            for (int nt = 0; nt < 8; nt++) mma16816(sacc[nt], qfl[ks], khf[nt]);
        }

        // mask + online softmax
        float rm0 = -1e30f, rm1 = -1e30f;
#pragma unroll
        for (int nt = 0; nt < 8; nt++) {
            int c0 = nt * 8 + (lane & 3) * 2;
            int ks0 = seqk[c0], ks1 = seqk[c0 + 1];
            sacc[nt][0] = (sq0 == ks0) ? sacc[nt][0] : -1e30f;
            sacc[nt][1] = (sq0 == ks1) ? sacc[nt][1] : -1e30f;
            sacc[nt][2] = (sq1 == ks0) ? sacc[nt][2] : -1e30f;
            sacc[nt][3] = (sq1 == ks1) ? sacc[nt][3] : -1e30f;
            rm0 = fmaxf(rm0, fmaxf(sacc[nt][0], sacc[nt][1]));
            rm1 = fmaxf(rm1, fmaxf(sacc[nt][2], sacc[nt][3]));
        }
        rm0 = fmaxf(rm0, __shfl_xor_sync(0xffffffffu, rm0, 1));
        rm0 = fmaxf(rm0, __shfl_xor_sync(0xffffffffu, rm0, 2));
        rm1 = fmaxf(rm1, __shfl_xor_sync(0xffffffffu, rm1, 1));
        rm1 = fmaxf(rm1, __shfl_xor_sync(0xffffffffu, rm1, 2));
        float mn0 = fmaxf(m0, rm0), mn1 = fmaxf(m1, rm1);
        float cf0 = __expf(m0 - mn0), cf1 = __expf(m1 - mn1);
        m0 = mn0; m1 = mn1;
        float rs0 = 0.f, rs1 = 0.f;
#pragma unroll
        for (int nt = 0; nt < 8; nt++) {
            float p0 = (sacc[nt][0] > -5e29f) ? __expf(sacc[nt][0] - mn0) : 0.f;
            float p1 = (sacc[nt][1] > -5e29f) ? __expf(sacc[nt][1] - mn0) : 0.f;
            float p2 = (sacc[nt][2] > -5e29f) ? __expf(sacc[nt][2] - mn1) : 0.f;
            float p3 = (sacc[nt][3] > -5e29f) ? __expf(sacc[nt][3] - mn1) : 0.f;
            sacc[nt][0] = p0; sacc[nt][1] = p1; sacc[nt][2] = p2; sacc[nt][3] = p3;
            rs0 += p0 + p1; rs1 += p2 + p3;
        }
        rs0 += __shfl_xor_sync(0xffffffffu, rs0, 1);
        rs0 += __shfl_xor_sync(0xffffffffu, rs0, 2);
        rs1 += __shfl_xor_sync(0xffffffffu, rs1, 1);
        rs1 += __shfl_xor_sync(0xffffffffu, rs1, 2);
        l0 = l0 * cf0 + rs0;
        l1 = l1 * cf1 + rs1;
#pragma unroll
        for (int nt = 0; nt < 8; nt++) {
            oacc[nt][0] *= cf0; oacc[nt][1] *= cf0;
            oacc[nt][2] *= cf1; oacc[nt][3] *= cf1;
        }

        // P -> bf16 hi/lo A-fragments (C layout maps directly to A layout)
        uint32_t pfh[4][4], pfl[4][4];
#pragma unroll
        for (int s = 0; s < 4; s++) {
#pragma unroll
            for (int half = 0; half < 2; half++) {
                int nt = 2 * s + half;
                float p0 = sacc[nt][0], p1 = sacc[nt][1];
                float p2 = sacc[nt][2], p3 = sacc[nt][3];
                __nv_bfloat16 h0 = __float2bfloat16(p0), h1 = __float2bfloat16(p1);
                __nv_bfloat16 h2 = __float2bfloat16(p2), h3 = __float2bfloat16(p3);
                pfh[s][half*2+0] = pack_bf2(p0, p1);
                pfh[s][half*2+1] = pack_bf2(p2, p3);
                pfl[s][half*2+0] = pack_bf2(p0 - __bfloat162float(h0), p1 - __bfloat162float(h1));
                pfl[s][half*2+1] = pack_bf2(p2 - __bfloat162float(h2), p3 - __bfloat162float(h3));
            }
        }

        // O += P V  (3-term split); B operand from Vt [d][kpos]
#pragma unroll
        for (int ks = 0; ks < 4; ks++) {
            uint32_t vhf[8][2], vlf[8][2];
#pragma unroll
            for (int nt = 0; nt < 8; nt++) {
                uint32_t rb = stb + 16384 + (uint32_t)((nt * 8 + brl) << 7)
                            + (((uint32_t)(ks * 32) + bh16) ^ bxor);
                ldsm2(vhf[nt], rb);
                ldsm2(vlf[nt], rb + 8192);
            }
#pragma unroll
            for (int nt = 0; nt < 8; nt++) mma16816(oacc[nt], pfh[ks], vhf[nt]);
#pragma unroll
            for (int nt = 0; nt < 8; nt++) mma16816(oacc[nt], pfh[ks], vlf[nt]);
#pragma unroll
            for (int nt = 0; nt < 8; nt++) mma16816(oacc[nt], pfl[ks], vhf[nt]);
        }
        __syncthreads();   // all warps done with this stage before it is overwritten
    }

    // epilogue: normalize + split to ctxh/ctxl  [B][L][H*64]
    float inv0 = 1.0f / l0, inv1 = 1.0f / l1;
#pragma unroll
    for (int nt = 0; nt < 8; nt++) {
        int col = h * 64 + nt * 8 + (lane & 3) * 2;
        size_t i0 = (size_t)(b * LL + q0 + r0) * DD + col;
        size_t i1 = (size_t)(b * LL + q0 + r0 + 8) * DD + col;
        float o0 = oacc[nt][0] * inv0, o1 = oacc[nt][1] * inv0;
        float o2 = oacc[nt][2] * inv1, o3 = oacc[nt][3] * inv1;
        __nv_bfloat16 h0 = __float2bfloat16(o0), h1 = __float2bfloat16(o1);
        __nv_bfloat16 h2 = __float2bfloat16(o2), h3 = __float2bfloat16(o3);
        *(uint32_t*)(ctxh + i0) = pack_bf2(o0, o1);
        *(uint32_t*)(ctxl + i0) = pack_bf2(o0 - __bfloat162float(h0), o1 - __bfloat162float(h1));
        *(uint32_t*)(ctxh + i1) = pack_bf2(o2, o3);
        *(uint32_t*)(ctxl + i1) = pack_bf2(o2 - __bfloat162float(h2), o3 - __bfloat162float(h3));
    }
}

// ---------------- launch ----------------
extern "C" void kernel_launch(void* const* d_in, const int* in_sizes, int n_in,
                              void* d_out, int out_size)
{
    const float* x     = (const float*)d_in[0];
    const int*   seq   = (const int*)  d_in[1];
    const float* ln1w  = (const float*)d_in[2];
    const float* ln1b  = (const float*)d_in[3];
    const float* wqkv  = (const float*)d_in[4];
    const float* qlnw  = (const float*)d_in[5];
    const float* klnw  = (const float*)d_in[6];
    const float* outw  = (const float*)d_in[7];
    float* out = (float*)d_out;

    float *qkv, *v;
    __nv_bfloat16 *qh, *ql, *kh, *kl, *vth, *vtl;
    __nv_bfloat16 *hh, *hl, *wqh, *wql, *ctxh, *ctxl, *owh, *owl;
    cudaGetSymbolAddress((void**)&qkv,  g_qkv);
    cudaGetSymbolAddress((void**)&v,    g_v);
    cudaGetSymbolAddress((void**)&qh,   g_qh);
    cudaGetSymbolAddress((void**)&ql,   g_ql);
    cudaGetSymbolAddress((void**)&kh,   g_kh);
    cudaGetSymbolAddress((void**)&kl,   g_kl);
    cudaGetSymbolAddress((void**)&vth,  g_vth);
    cudaGetSymbolAddress((void**)&vtl,  g_vtl);
    cudaGetSymbolAddress((void**)&hh,   g_hh);
    cudaGetSymbolAddress((void**)&hl,   g_hl);
    cudaGetSymbolAddress((void**)&wqh,  g_wqh);
    cudaGetSymbolAddress((void**)&wql,  g_wql);
    cudaGetSymbolAddress((void**)&ctxh, g_ctxh);
    cudaGetSymbolAddress((void**)&ctxl, g_ctxl);
    cudaGetSymbolAddress((void**)&owh,  g_owh);
    cudaGetSymbolAddress((void**)&owl,  g_owl);

    cudaFuncSetAttribute(gemm_bf16s, cudaFuncAttributeMaxDynamicSharedMemorySize,
                         GEMM_SMEM);
    cudaFuncSetAttribute(attn_mma, cudaFuncAttributeMaxDynamicSharedMemorySize,
                         ATT_SMEM);

    ln1_split_kernel<<<ROWS, 256>>>(x, ln1w, ln1b, hh, hl);
    split_kernel<<<3*DD*DD/1024, 256>>>(wqkv, wqh, wql);
    gemm_bf16s<<<dim3(3*DD/128, ROWS/128), 256, GEMM_SMEM>>>(
        hh, hl, wqh, wql, qkv, ROWS, 3*DD, DD);
    qk_rope_kernel<<<ROWS, 256>>>(qkv, qlnw, klnw, qh, ql, kh, kl, v);
    v_trans_kernel<<<dim3(LL/64, BB*HH), 256>>>(v, vth, vtl);
    attn_mma<<<dim3(LL/128, BB*HH), 256, ATT_SMEM>>>(
        qh, ql, kh, kl, vth, vtl, seq, ctxh, ctxl);
    split_kernel<<<DD*DD/1024, 256>>>(outw, owh, owl);
    gemm_bf16s<<<dim3(DD/128, ROWS/128), 256, GEMM_SMEM>>>(
        ctxh, ctxl, owh, owl, out, ROWS, DD, DD);
}